// round 13
// baseline (speedup 1.0000x reference)
#include <cuda_runtime.h>
#include <cuda_bf16.h>
#include <cuda_fp16.h>
#include <cstdint>

#define NN 50000
#define EE 500000

// ---------------- device scratch (no allocs allowed) ----------------
__device__ __align__(16) __half g_h16 [NN*64];
__device__ __align__(16) __half g_hn16[NN*64];
__device__ __align__(16) __half g_q16[NN*256];
__device__ __align__(16) __half g_kv [NN*512];   // per node: k[0,256), v[256,512)
__device__ __align__(16) __half g_s16[NN*64];
__device__ __align__(16) __half g_w16[4*13*4096]; // fp16 weights [l][t][n][k]
__device__ int   g_deg[NN];
__device__ int   g_rowptr[NN+1];
__device__ int   g_cursor[NN];
__device__ int   g_srcs[EE];

__device__ __forceinline__ float elu(float x){ return x > 0.f ? x : (__expf(x) - 1.f); }

__device__ __forceinline__ void mma_f16(float* d, const uint32_t* a, uint32_t b0, uint32_t b1){
    asm volatile("mma.sync.aligned.m16n8k16.row.col.f32.f16.f16.f32 "
        "{%0,%1,%2,%3}, {%4,%5,%6,%7}, {%8,%9}, {%0,%1,%2,%3};"
        : "+f"(d[0]), "+f"(d[1]), "+f"(d[2]), "+f"(d[3])
        : "r"(a[0]), "r"(a[1]), "r"(a[2]), "r"(a[3]), "r"(b0), "r"(b1));
}

__device__ __forceinline__ void ldsm_x4(uint32_t* r, uint32_t addr){
    asm volatile("ldmatrix.sync.aligned.m8n8.x4.shared.b16 {%0,%1,%2,%3}, [%4];"
        : "=r"(r[0]), "=r"(r[1]), "=r"(r[2]), "=r"(r[3]) : "r"(addr));
}

__device__ __forceinline__ uint32_t smem_u32(const void* p){
    return (uint32_t)__cvta_generic_to_shared(p);
}

// ---------------- weight pre-conversion + deg zero (fused) ----------------
__global__ void k_wconv(const float* __restrict__ Wq, const float* __restrict__ Wk,
                        const float* __restrict__ Wv, const float* __restrict__ Ws){
    int idx = blockIdx.x*blockDim.x + threadIdx.x;   // over 4*13*4096 = 212992
    if (idx < NN) g_deg[idx] = 0;
    if (idx >= 4*13*4096) return;
    int l = idx / (13*4096);
    int r = idx % (13*4096);
    int t = r / 4096;
    int i = r % 4096;
    float v;
    if (t < 4)       v = Wq[l*16384 + t*4096 + i];
    else if (t < 8)  v = Wk[l*16384 + (t-4)*4096 + i];
    else if (t < 12) v = Wv[l*16384 + (t-8)*4096 + i];
    else             v = Ws[l*4096 + i];
    g_w16[idx] = __float2half(v);
}

// ---------------- CSR build ----------------
__global__ void k_hist(const int* __restrict__ ei){
    int e = blockIdx.x*blockDim.x + threadIdx.x;
    if (e < EE) atomicAdd(&g_deg[ei[EE + e]], 1);
}

// single block, 1024 threads: per-thread chunk of 49, one block scan
__global__ void k_scan(){
    const int PER = 49;   // 1024*49 = 50176 >= NN
    __shared__ int wsum[32];
    int tid = threadIdx.x, lane = tid & 31, wid = tid >> 5;
    int base = tid * PER;

    int sum = 0;
    #pragma unroll 8
    for (int i = 0; i < PER; i++){
        int idx = base + i;
        if (idx < NN) sum += g_deg[idx];
    }
    int incl = sum;
    #pragma unroll
    for (int d = 1; d < 32; d <<= 1){
        int t = __shfl_up_sync(0xffffffffu, incl, d);
        if (lane >= d) incl += t;
    }
    if (lane == 31) wsum[wid] = incl;
    __syncthreads();
    if (wid == 0){
        int wv = wsum[lane];
        int wi = wv;
        #pragma unroll
        for (int d = 1; d < 32; d <<= 1){
            int t = __shfl_up_sync(0xffffffffu, wi, d);
            if (lane >= d) wi += t;
        }
        wsum[lane] = wi - wv;   // exclusive
    }
    __syncthreads();
    int run = wsum[wid] + incl - sum;   // exclusive offset for this thread

    #pragma unroll 8
    for (int i = 0; i < PER; i++){
        int idx = base + i;
        if (idx < NN){
            g_rowptr[idx] = run;
            g_cursor[idx] = run;
            run += g_deg[idx];
        }
    }
    if (tid == 1023) g_rowptr[NN] = run;
}

__global__ void k_fill(const int* __restrict__ ei){
    int e = blockIdx.x*blockDim.x + threadIdx.x;
    if (e < EE){
        int d = ei[EE + e];
        int p = atomicAdd(&g_cursor[d], 1);
        g_srcs[p] = ei[e];
    }
}

// ---------------- encoder: x(N,8) -> h(N,64), two ELU linears ----------------
__global__ void k_encoder(const float* __restrict__ x,
                          const float* __restrict__ w1, const float* __restrict__ b1,
                          const float* __restrict__ w2, const float* __restrict__ b2){
    __shared__ float sw1[8*64];    // [k][u]
    __shared__ float sw2[64*64];   // [k][u]
    __shared__ float sb1[64], sb2[64];
    __shared__ float st1[4][64];
    int tid = threadIdx.x;
    #pragma unroll
    for (int i = 0; i < 2; i++){
        int idx = tid + i*256;
        int u = idx >> 3, k = idx & 7;
        sw1[k*64 + u] = w1[idx];
    }
    #pragma unroll
    for (int i = 0; i < 16; i++){
        int idx = tid + i*256;
        sw2[(idx & 63)*64 + (idx >> 6)] = w2[idx];
    }
    if (tid < 64){ sb1[tid] = b1[tid]; sb2[tid] = b2[tid]; }
    __syncthreads();

    int u = tid & 63, nl = tid >> 6;
    int n0 = blockIdx.x * 64;
    for (int it = 0; it < 16; ++it){
        int n = n0 + it*4 + nl;
        float t1 = 0.f;
        if (n < NN){
            float s = sb1[u];
            #pragma unroll
            for (int k = 0; k < 8; k++) s += x[n*8 + k] * sw1[k*64 + u];
            t1 = elu(s);
        }
        st1[nl][u] = t1;
        __syncthreads();
        if (n < NN){
            float s = sb2[u];
            #pragma unroll
            for (int k = 0; k < 64; k++) s += st1[nl][k] * sw2[k*64 + u];
            g_h16[n*64 + u] = __float2half(elu(s));
        }
        __syncthreads();
    }
}

// ---------------- per-layer q/k/v/skip GEMM: fp16 mma m16n8k16 + ldmatrix ----------------
__global__ __launch_bounds__(256) void k_gemm(int layer, int pp,
                       const float* __restrict__ bq, const float* __restrict__ bk,
                       const float* __restrict__ bv, const float* __restrict__ bs){
    const __half* hin = pp ? g_hn16 : g_h16;
    int t = blockIdx.y;
    const __half* W = &g_w16[(layer*13 + t)*4096];
    const float* bias; __half* out; int ldo, coff;
    if (t < 4)      { bias = bq + t*64;      out = g_q16; ldo = 256; coff = t*64; }
    else if (t < 8) { bias = bk + (t-4)*64;  out = g_kv;  ldo = 512; coff = (t-4)*64; }
    else if (t <12) { bias = bv + (t-8)*64;  out = g_kv;  ldo = 512; coff = 256 + (t-8)*64; }
    else            { bias = bs;             out = g_s16; ldo = 64;  coff = 0; }

    __shared__ uint32_t sA[128*36];
    __shared__ uint32_t sB[64*36];
    int tid = threadIdx.x;
    int m0 = blockIdx.x * 128;

    #pragma unroll
    for (int i = 0; i < 4; i++){
        int idx = tid + i*256;
        int row = idx >> 3;
        int c8  = idx & 7;
        uint4 va = make_uint4(0,0,0,0);
        if (m0 + row < NN) va = *(const uint4*)&hin[(m0 + row)*64 + c8*8];
        *(uint4*)&sA[row*36 + c8*4] = va;
    }
    #pragma unroll
    for (int i = 0; i < 2; i++){
        int idx = tid + i*256;
        int row = idx >> 3;
        int c8  = idx & 7;
        uint4 vb = *(const uint4*)&W[row*64 + c8*8];
        *(uint4*)&sB[row*36 + c8*4] = vb;
    }
    __syncthreads();

    int wid = tid >> 5, lane = tid & 31;
    int g = lane >> 2, t4 = lane & 3;
    int wr = wid * 16;

    uint32_t aBase = smem_u32(sA) + (((wr + (lane & 15))*36 + ((lane & 16) ? 4 : 0)) << 2);
    uint32_t bBase = smem_u32(sB) + (((((lane >> 4) & 1)*8 + (lane & 7))*36 + ((lane >> 3) & 1)*4) << 2);

    float acc[8][4] = {};

    #pragma unroll
    for (int kc = 0; kc < 4; kc++){
        uint32_t a[4];
        ldsm_x4(a, aBase + kc*32);
        #pragma unroll
        for (int nt2 = 0; nt2 < 8; nt2 += 2){
            uint32_t b[4];
            ldsm_x4(b, bBase + nt2*1152 + kc*32);
            mma_f16(acc[nt2],   a, b[0], b[1]);
            mma_f16(acc[nt2+1], a, b[2], b[3]);
        }
    }

    // staged epilogue: regs -> smem (conflict-free) -> coalesced uint4 stores
    __syncthreads();
    __half* sOut = (__half*)sA;
    {
        int r0 = wr + g;
        #pragma unroll
        for (int nt = 0; nt < 8; nt++){
            int col = nt*8 + t4*2;
            float bz0 = bias[col], bz1 = bias[col+1];
            *(__half2*)&sOut[r0*72 + col]     = __floats2half2_rn(acc[nt][0] + bz0, acc[nt][1] + bz1);
            *(__half2*)&sOut[(r0+8)*72 + col] = __floats2half2_rn(acc[nt][2] + bz0, acc[nt][3] + bz1);
        }
    }
    __syncthreads();
    #pragma unroll
    for (int i = 0; i < 4; i++){
        int idx = tid + i*256;
        int row = idx >> 3;
        int c8  = idx & 7;
        if (m0 + row < NN)
            *(uint4*)&out[(m0 + row)*ldo + coff + c8*8] = *(uint4*)&sOut[row*72 + c8*8];
    }
}

// ---------------- edge kernel: per-dst warp, independent-edge softmax ----------------
__global__ void k_edge(int pp){
    int gw = (blockIdx.x*blockDim.x + threadIdx.x) >> 5;
    int lane = threadIdx.x & 31;
    if (gw >= NN) return;
    int dst = gw;
    __half* hout = pp ? g_h16 : g_hn16;

    uint4 qr = *(const uint4*)&g_q16[dst*256 + lane*8];
    __half2 sc = __float2half2_rn(0.125f);
    __half2 qh0 = __hmul2(*(__half2*)&qr.x, sc);
    __half2 qh1 = __hmul2(*(__half2*)&qr.y, sc);
    __half2 qh2 = __hmul2(*(__half2*)&qr.z, sc);
    __half2 qh3 = __hmul2(*(__half2*)&qr.w, sc);

    int beg = g_rowptr[dst], end = g_rowptr[dst+1];

    float ssum = 0.f;
    float acc[8] = {0,0,0,0,0,0,0,0};

    #pragma unroll 4
    for (int p = beg; p < end; p++){
        int s = g_srcs[p];
        uint4 kr = *(const uint4*)&g_kv[s*512 + lane*8];
        uint4 vr = *(const uint4*)&g_kv[s*512 + 256 + lane*8];
        __half2 d2 = __hmul2(qh0, *(__half2*)&kr.x);
        d2 = __hfma2(qh1, *(__half2*)&kr.y, d2);
        d2 = __hfma2(qh2, *(__half2*)&kr.z, d2);
        d2 = __hfma2(qh3, *(__half2*)&kr.w, d2);
        float2 df = __half22float2(d2);
        float d = df.x + df.y;
        d += __shfl_xor_sync(0xffffffffu, d, 1);
        d += __shfl_xor_sync(0xffffffffu, d, 2);
        d += __shfl_xor_sync(0xffffffffu, d, 4);
        float e = __expf(d);
        ssum += e;
        float2 v0 = __half22float2(*(__half2*)&vr.x);
        float2 v1 = __half22float2(*(__half2*)&vr.y);
        float2 v2 = __half22float2(*(__half2*)&vr.z);
        float2 v3 = __half22float2(*(__half2*)&vr.w);
        acc[0] += e*v0.x; acc[1] += e*v0.y;
        acc[2] += e*v1.x; acc[3] += e*v1.y;
        acc[4] += e*v2.x; acc[5] += e*v2.y;
        acc[6] += e*v3.x; acc[7] += e*v3.y;
    }

    float inv = (end > beg) ? 1.f / ssum : 0.f;
    #pragma unroll
    for (int j = 0; j < 8; j++){
        float aj = acc[j] * inv;
        aj += __shfl_xor_sync(0xffffffffu, aj, 8);
        aj += __shfl_xor_sync(0xffffffffu, aj, 16);
        acc[j] = aj;
    }
    if (lane < 8){
        #pragma unroll
        for (int j = 0; j < 8; j++){
            int c = lane*8 + j;
            float o = acc[j]*0.25f + __half2float(g_s16[dst*64 + c]);
            hout[dst*64 + c] = __float2half(elu(o));
        }
    }
}

// ---------------- output MLP: 64 -> 64 -> 32 -> 8 ----------------
__global__ void k_out(const float* __restrict__ w1, const float* __restrict__ b1,
                      const float* __restrict__ w2, const float* __restrict__ b2,
                      const float* __restrict__ w3, const float* __restrict__ b3,
                      float* __restrict__ out){
    __shared__ float sw1[64*64];
    __shared__ float sw2[64*32];
    __shared__ float sw3[32*8];
    __shared__ float sb1[64], sb2[32], sb3[8];
    __shared__ float so1[4][64];
    __shared__ float so2[4][32];
    int tid = threadIdx.x;
    #pragma unroll
    for (int i = 0; i < 16; i++){
        int idx = tid + i*256;
        sw1[(idx & 63)*64 + (idx >> 6)] = w1[idx];
    }
    #pragma unroll
    for (int i = 0; i < 8; i++){
        int idx = tid + i*256;
        sw2[(idx & 63)*32 + (idx >> 6)] = w2[idx];
    }
    { int idx = tid;
      sw3[(idx & 31)*8 + (idx >> 5)] = w3[idx]; }
    if (tid < 64) sb1[tid] = b1[tid];
    if (tid < 32) sb2[tid] = b2[tid];
    if (tid < 8)  sb3[tid] = b3[tid];
    __syncthreads();

    int u = tid & 63, nl = tid >> 6;
    int n0 = blockIdx.x * 32;
    for (int it = 0; it < 8; ++it){
        int n = n0 + it*4 + nl;
        float o1v = 0.f;
        if (n < NN){
            float s = sb1[u];
            #pragma unroll
            for (int k = 0; k < 64; k++) s += __half2float(g_h16[n*64 + k]) * sw1[k*64 + u];
            o1v = elu(s);
        }
        so1[nl][u] = o1v;
        __syncthreads();
        if (u < 32 && n < NN){
            float s = sb2[u];
            #pragma unroll
            for (int k = 0; k < 64; k++) s += so1[nl][k] * sw2[k*32 + u];
            so2[nl][u] = elu(s);
        }
        __syncthreads();
        if (u < 8 && n < NN){
            float s = sb3[u];
            #pragma unroll
            for (int k = 0; k < 32; k++) s += so2[nl][k] * sw3[k*8 + u];
            out[n*8 + u] = s;
        }
        __syncthreads();
    }
}

// ---------------- launch ----------------
extern "C" void kernel_launch(void* const* d_in, const int* in_sizes, int n_in,
                              void* d_out, int out_size){
    const float* x   = (const float*)d_in[0];
    const int*   ei  = (const int*)d_in[1];
    const float* enc_w1 = (const float*)d_in[2];
    const float* enc_b1 = (const float*)d_in[3];
    const float* enc_w2 = (const float*)d_in[4];
    const float* enc_b2 = (const float*)d_in[5];
    const float* Wq = (const float*)d_in[6];
    const float* bq = (const float*)d_in[7];
    const float* Wk = (const float*)d_in[8];
    const float* bk = (const float*)d_in[9];
    const float* Wv = (const float*)d_in[10];
    const float* bv = (const float*)d_in[11];
    const float* Ws = (const float*)d_in[12];
    const float* bs = (const float*)d_in[13];
    const float* ow1 = (const float*)d_in[14];
    const float* ob1 = (const float*)d_in[15];
    const float* ow2 = (const float*)d_in[16];
    const float* ob2 = (const float*)d_in[17];
    const float* ow3 = (const float*)d_in[18];
    const float* ob3 = (const float*)d_in[19];
    float* out = (float*)d_out;

    dim3 ggrid((NN+127)/128, 13);

    // ordered so launch index 3 (the one ncu captures) is the layer-0 GEMM
    k_wconv<<<(4*13*4096+255)/256, 256>>>(Wq, Wk, Wv, Ws);          // 0 (+ deg zero)
    k_hist<<<(EE+255)/256, 256>>>(ei);                              // 1
    k_encoder<<<(NN+63)/64, 256>>>(x, enc_w1, enc_b1, enc_w2, enc_b2); // 2
    k_gemm<<<ggrid, 256>>>(0, 0, bq, bk, bv, bs);                   // 3 <- ncu
    k_scan<<<1, 1024>>>();                                          // 4
    k_fill<<<(EE+255)/256, 256>>>(ei);                              // 5
    k_edge<<<(NN*32 + 255)/256, 256>>>(0);                          // 6

    for (int l = 1; l < 4; l++){
        int pp = l & 1;
        k_gemm<<<ggrid, 256>>>(l, pp, bq + l*256, bk + l*256, bv + l*256, bs + l*64);
        k_edge<<<(NN*32 + 255)/256, 256>>>(pp);
    }

    // output MLP (final h is in g_h16 after layer 3)
    k_out<<<(NN+31)/32, 256>>>(ow1, ob1, ow2, ob2, ow3, ob3, out);
}

// round 14
// speedup vs baseline: 1.0469x; 1.0469x over previous
#include <cuda_runtime.h>
#include <cuda_bf16.h>
#include <cuda_fp16.h>
#include <cstdint>

#define NN 50000
#define EE 500000

// ---------------- device scratch (no allocs allowed) ----------------
__device__ __align__(16) __half g_h16 [NN*64];
__device__ __align__(16) __half g_hn16[NN*64];
__device__ __align__(16) __half g_q16[NN*256];
__device__ __align__(16) __half g_kv [NN*512];   // per node: k[0,256), v[256,512)
__device__ __align__(16) __half g_s16[NN*64];
__device__ __align__(16) __half g_w16[4*13*4096]; // fp16 weights [l][t][n][k]
__device__ int   g_deg[NN];
__device__ int   g_rowptr[NN+1];
__device__ int   g_cursor[NN];
__device__ int   g_srcs[EE];

__device__ __forceinline__ float elu(float x){ return x > 0.f ? x : (__expf(x) - 1.f); }

__device__ __forceinline__ void mma_f16(float* d, const uint32_t* a, uint32_t b0, uint32_t b1){
    asm volatile("mma.sync.aligned.m16n8k16.row.col.f32.f16.f16.f32 "
        "{%0,%1,%2,%3}, {%4,%5,%6,%7}, {%8,%9}, {%0,%1,%2,%3};"
        : "+f"(d[0]), "+f"(d[1]), "+f"(d[2]), "+f"(d[3])
        : "r"(a[0]), "r"(a[1]), "r"(a[2]), "r"(a[3]), "r"(b0), "r"(b1));
}

__device__ __forceinline__ void ldsm_x4(uint32_t* r, uint32_t addr){
    asm volatile("ldmatrix.sync.aligned.m8n8.x4.shared.b16 {%0,%1,%2,%3}, [%4];"
        : "=r"(r[0]), "=r"(r[1]), "=r"(r[2]), "=r"(r[3]) : "r"(addr));
}

__device__ __forceinline__ uint32_t smem_u32(const void* p){
    return (uint32_t)__cvta_generic_to_shared(p);
}

// ---------------- weight pre-conversion + deg zero (fused) ----------------
__global__ void k_wconv(const float* __restrict__ Wq, const float* __restrict__ Wk,
                        const float* __restrict__ Wv, const float* __restrict__ Ws){
    int idx = blockIdx.x*blockDim.x + threadIdx.x;   // over 4*13*4096 = 212992
    if (idx < NN) g_deg[idx] = 0;
    if (idx >= 4*13*4096) return;
    int l = idx / (13*4096);
    int r = idx % (13*4096);
    int t = r / 4096;
    int i = r % 4096;
    float v;
    if (t < 4)       v = Wq[l*16384 + t*4096 + i];
    else if (t < 8)  v = Wk[l*16384 + (t-4)*4096 + i];
    else if (t < 12) v = Wv[l*16384 + (t-8)*4096 + i];
    else             v = Ws[l*4096 + i];
    g_w16[idx] = __float2half(v);
}

// ---------------- CSR build ----------------
__global__ void k_hist(const int* __restrict__ ei){
    int e = blockIdx.x*blockDim.x + threadIdx.x;
    if (e < EE) atomicAdd(&g_deg[ei[EE + e]], 1);
}

// coalesced barrier-round scan (proven in the 590us config)
__global__ void k_scan(){
    __shared__ int wexc[32], wtot[32];
    __shared__ int s_off;
    int tid = threadIdx.x, lane = tid & 31, wid = tid >> 5;
    if (tid == 0) s_off = 0;
    __syncthreads();
    for (int base = 0; base < NN; base += 1024){
        int i = base + tid;
        int v = (i < NN) ? g_deg[i] : 0;
        int incl = v;
        #pragma unroll
        for (int d = 1; d < 32; d <<= 1){
            int t = __shfl_up_sync(0xffffffffu, incl, d);
            if (lane >= d) incl += t;
        }
        if (lane == 31) wtot[wid] = incl;
        __syncthreads();
        if (wid == 0){
            int wv = wtot[lane];
            int wi = wv;
            #pragma unroll
            for (int d = 1; d < 32; d <<= 1){
                int t = __shfl_up_sync(0xffffffffu, wi, d);
                if (lane >= d) wi += t;
            }
            wexc[lane] = wi - wv;
        }
        __syncthreads();
        int excl = s_off + wexc[wid] + incl - v;
        if (i < NN){ g_rowptr[i] = excl; g_cursor[i] = excl; }
        __syncthreads();
        if (tid == 0) s_off += wexc[31] + wtot[31];
        __syncthreads();
    }
    if (tid == 0) g_rowptr[NN] = s_off;
}

__global__ void k_fill(const int* __restrict__ ei){
    int e = blockIdx.x*blockDim.x + threadIdx.x;
    if (e < EE){
        int d = ei[EE + e];
        int p = atomicAdd(&g_cursor[d], 1);
        g_srcs[p] = ei[e];
    }
}

// ---------------- encoder: x(N,8) -> h(N,64), two ELU linears ----------------
__global__ void k_encoder(const float* __restrict__ x,
                          const float* __restrict__ w1, const float* __restrict__ b1,
                          const float* __restrict__ w2, const float* __restrict__ b2){
    __shared__ float sw1[8*64];    // [k][u]
    __shared__ float sw2[64*64];   // [k][u]
    __shared__ float sb1[64], sb2[64];
    __shared__ float st1[4][64];
    int tid = threadIdx.x;
    #pragma unroll
    for (int i = 0; i < 2; i++){
        int idx = tid + i*256;
        int u = idx >> 3, k = idx & 7;
        sw1[k*64 + u] = w1[idx];
    }
    #pragma unroll
    for (int i = 0; i < 16; i++){
        int idx = tid + i*256;
        sw2[(idx & 63)*64 + (idx >> 6)] = w2[idx];
    }
    if (tid < 64){ sb1[tid] = b1[tid]; sb2[tid] = b2[tid]; }
    __syncthreads();

    int u = tid & 63, nl = tid >> 6;
    int n0 = blockIdx.x * 64;
    for (int it = 0; it < 16; ++it){
        int n = n0 + it*4 + nl;
        float t1 = 0.f;
        if (n < NN){
            float s = sb1[u];
            #pragma unroll
            for (int k = 0; k < 8; k++) s += x[n*8 + k] * sw1[k*64 + u];
            t1 = elu(s);
        }
        st1[nl][u] = t1;
        __syncthreads();
        if (n < NN){
            float s = sb2[u];
            #pragma unroll
            for (int k = 0; k < 64; k++) s += st1[nl][k] * sw2[k*64 + u];
            g_h16[n*64 + u] = __float2half(elu(s));
        }
        __syncthreads();
    }
}

// ---------------- per-layer q/k/v/skip GEMM: fp16 mma m16n8k16 + ldmatrix ----------------
// M-tile = 256 rows per block (8 warps x 32 rows): each B ldmatrix feeds TWO
// 16-row m-groups -> 40% fewer B-fragment loads per output row.
__global__ __launch_bounds__(256) void k_gemm(int layer, int pp,
                       const float* __restrict__ bq, const float* __restrict__ bk,
                       const float* __restrict__ bv, const float* __restrict__ bs){
    const __half* hin = pp ? g_hn16 : g_h16;
    int t = blockIdx.y;
    const __half* W = &g_w16[(layer*13 + t)*4096];
    const float* bias; __half* out; int ldo, coff;
    if (t < 4)      { bias = bq + t*64;      out = g_q16; ldo = 256; coff = t*64; }
    else if (t < 8) { bias = bk + (t-4)*64;  out = g_kv;  ldo = 512; coff = (t-4)*64; }
    else if (t <12) { bias = bv + (t-8)*64;  out = g_kv;  ldo = 512; coff = 256 + (t-8)*64; }
    else            { bias = bs;             out = g_s16; ldo = 64;  coff = 0; }

    __shared__ uint32_t sA[256*36];  // 36,864B
    __shared__ uint32_t sB[64*36];   //  9,216B
    int tid = threadIdx.x;
    int m0 = blockIdx.x * 256;

    #pragma unroll
    for (int i = 0; i < 8; i++){
        int idx = tid + i*256;           // 0..2047 over 256 rows x 8 uint4
        int row = idx >> 3;
        int c8  = idx & 7;
        uint4 va = make_uint4(0,0,0,0);
        if (m0 + row < NN) va = *(const uint4*)&hin[(m0 + row)*64 + c8*8];
        *(uint4*)&sA[row*36 + c8*4] = va;
    }
    #pragma unroll
    for (int i = 0; i < 2; i++){
        int idx = tid + i*256;
        int row = idx >> 3;
        int c8  = idx & 7;
        uint4 vb = *(const uint4*)&W[row*64 + c8*8];
        *(uint4*)&sB[row*36 + c8*4] = vb;
    }
    __syncthreads();

    int wid = tid >> 5, lane = tid & 31;
    int g = lane >> 2, t4 = lane & 3;
    int wr = wid * 32;

    uint32_t aBase0 = smem_u32(sA) + (((wr      + (lane & 15))*36 + ((lane & 16) ? 4 : 0)) << 2);
    uint32_t aBase1 = smem_u32(sA) + (((wr + 16 + (lane & 15))*36 + ((lane & 16) ? 4 : 0)) << 2);
    uint32_t bBase  = smem_u32(sB) + (((((lane >> 4) & 1)*8 + (lane & 7))*36 + ((lane >> 3) & 1)*4) << 2);

    float acc0[8][4] = {};
    float acc1[8][4] = {};

    #pragma unroll
    for (int kc = 0; kc < 4; kc++){
        uint32_t a0[4], a1[4];
        ldsm_x4(a0, aBase0 + kc*32);
        ldsm_x4(a1, aBase1 + kc*32);
        #pragma unroll
        for (int nt2 = 0; nt2 < 8; nt2 += 2){
            uint32_t b[4];
            ldsm_x4(b, bBase + nt2*1152 + kc*32);
            mma_f16(acc0[nt2],   a0, b[0], b[1]);
            mma_f16(acc0[nt2+1], a0, b[2], b[3]);
            mma_f16(acc1[nt2],   a1, b[0], b[1]);
            mma_f16(acc1[nt2+1], a1, b[2], b[3]);
        }
    }

    // staged epilogue: regs -> smem (conflict-free) -> coalesced uint4 stores
    __syncthreads();
    __half* sOut = (__half*)sA;         // 256 rows x 72-half pitch
    {
        int r0 = wr + g;
        #pragma unroll
        for (int nt = 0; nt < 8; nt++){
            int col = nt*8 + t4*2;
            float bz0 = bias[col], bz1 = bias[col+1];
            *(__half2*)&sOut[r0*72 + col]      = __floats2half2_rn(acc0[nt][0] + bz0, acc0[nt][1] + bz1);
            *(__half2*)&sOut[(r0+8)*72 + col]  = __floats2half2_rn(acc0[nt][2] + bz0, acc0[nt][3] + bz1);
            *(__half2*)&sOut[(r0+16)*72 + col] = __floats2half2_rn(acc1[nt][0] + bz0, acc1[nt][1] + bz1);
            *(__half2*)&sOut[(r0+24)*72 + col] = __floats2half2_rn(acc1[nt][2] + bz0, acc1[nt][3] + bz1);
        }
    }
    __syncthreads();
    #pragma unroll
    for (int i = 0; i < 8; i++){
        int idx = tid + i*256;          // 0..2047 over 256 rows x 8 uint4
        int row = idx >> 3;
        int c8  = idx & 7;
        if (m0 + row < NN)
            *(uint4*)&out[(m0 + row)*ldo + coff + c8*8] = *(uint4*)&sOut[row*72 + c8*8];
    }
}

// ---------------- edge kernel: per-dst warp, independent-edge softmax ----------------
__global__ void k_edge(int pp){
    int gw = (blockIdx.x*blockDim.x + threadIdx.x) >> 5;
    int lane = threadIdx.x & 31;
    if (gw >= NN) return;
    int dst = gw;
    __half* hout = pp ? g_h16 : g_hn16;

    uint4 qr = *(const uint4*)&g_q16[dst*256 + lane*8];
    __half2 sc = __float2half2_rn(0.125f);
    __half2 qh0 = __hmul2(*(__half2*)&qr.x, sc);
    __half2 qh1 = __hmul2(*(__half2*)&qr.y, sc);
    __half2 qh2 = __hmul2(*(__half2*)&qr.z, sc);
    __half2 qh3 = __hmul2(*(__half2*)&qr.w, sc);

    int beg = g_rowptr[dst], end = g_rowptr[dst+1];

    float ssum = 0.f;
    float acc[8] = {0,0,0,0,0,0,0,0};

    #pragma unroll 4
    for (int p = beg; p < end; p++){
        int s = g_srcs[p];
        uint4 kr = *(const uint4*)&g_kv[s*512 + lane*8];
        uint4 vr = *(const uint4*)&g_kv[s*512 + 256 + lane*8];
        __half2 d2 = __hmul2(qh0, *(__half2*)&kr.x);
        d2 = __hfma2(qh1, *(__half2*)&kr.y, d2);
        d2 = __hfma2(qh2, *(__half2*)&kr.z, d2);
        d2 = __hfma2(qh3, *(__half2*)&kr.w, d2);
        float2 df = __half22float2(d2);
        float d = df.x + df.y;
        d += __shfl_xor_sync(0xffffffffu, d, 1);
        d += __shfl_xor_sync(0xffffffffu, d, 2);
        d += __shfl_xor_sync(0xffffffffu, d, 4);
        float e = __expf(d);
        ssum += e;
        float2 v0 = __half22float2(*(__half2*)&vr.x);
        float2 v1 = __half22float2(*(__half2*)&vr.y);
        float2 v2 = __half22float2(*(__half2*)&vr.z);
        float2 v3 = __half22float2(*(__half2*)&vr.w);
        acc[0] += e*v0.x; acc[1] += e*v0.y;
        acc[2] += e*v1.x; acc[3] += e*v1.y;
        acc[4] += e*v2.x; acc[5] += e*v2.y;
        acc[6] += e*v3.x; acc[7] += e*v3.y;
    }

    float inv = (end > beg) ? 1.f / ssum : 0.f;
    #pragma unroll
    for (int j = 0; j < 8; j++){
        float aj = acc[j] * inv;
        aj += __shfl_xor_sync(0xffffffffu, aj, 8);
        aj += __shfl_xor_sync(0xffffffffu, aj, 16);
        acc[j] = aj;
    }
    if (lane < 8){
        #pragma unroll
        for (int j = 0; j < 8; j++){
            int c = lane*8 + j;
            float o = acc[j]*0.25f + __half2float(g_s16[dst*64 + c]);
            hout[dst*64 + c] = __float2half(elu(o));
        }
    }
}

// ---------------- output MLP: 64 -> 64 -> 32 -> 8 ----------------
__global__ void k_out(const float* __restrict__ w1, const float* __restrict__ b1,
                      const float* __restrict__ w2, const float* __restrict__ b2,
                      const float* __restrict__ w3, const float* __restrict__ b3,
                      float* __restrict__ out){
    __shared__ float sw1[64*64];
    __shared__ float sw2[64*32];
    __shared__ float sw3[32*8];
    __shared__ float sb1[64], sb2[32], sb3[8];
    __shared__ float so1[4][64];
    __shared__ float so2[4][32];
    int tid = threadIdx.x;
    #pragma unroll
    for (int i = 0; i < 16; i++){
        int idx = tid + i*256;
        sw1[(idx & 63)*64 + (idx >> 6)] = w1[idx];
    }
    #pragma unroll
    for (int i = 0; i < 8; i++){
        int idx = tid + i*256;
        sw2[(idx & 63)*32 + (idx >> 6)] = w2[idx];
    }
    { int idx = tid;
      sw3[(idx & 31)*8 + (idx >> 5)] = w3[idx]; }
    if (tid < 64) sb1[tid] = b1[tid];
    if (tid < 32) sb2[tid] = b2[tid];
    if (tid < 8)  sb3[tid] = b3[tid];
    __syncthreads();

    int u = tid & 63, nl = tid >> 6;
    int n0 = blockIdx.x * 32;
    for (int it = 0; it < 8; ++it){
        int n = n0 + it*4 + nl;
        float o1v = 0.f;
        if (n < NN){
            float s = sb1[u];
            #pragma unroll
            for (int k = 0; k < 64; k++) s += __half2float(g_h16[n*64 + k]) * sw1[k*64 + u];
            o1v = elu(s);
        }
        so1[nl][u] = o1v;
        __syncthreads();
        if (u < 32 && n < NN){
            float s = sb2[u];
            #pragma unroll
            for (int k = 0; k < 64; k++) s += so1[nl][k] * sw2[k*32 + u];
            so2[nl][u] = elu(s);
        }
        __syncthreads();
        if (u < 8 && n < NN){
            float s = sb3[u];
            #pragma unroll
            for (int k = 0; k < 32; k++) s += so2[nl][k] * sw3[k*8 + u];
            out[n*8 + u] = s;
        }
        __syncthreads();
    }
}

// ---------------- launch ----------------
extern "C" void kernel_launch(void* const* d_in, const int* in_sizes, int n_in,
                              void* d_out, int out_size){
    const float* x   = (const float*)d_in[0];
    const int*   ei  = (const int*)d_in[1];
    const float* enc_w1 = (const float*)d_in[2];
    const float* enc_b1 = (const float*)d_in[3];
    const float* enc_w2 = (const float*)d_in[4];
    const float* enc_b2 = (const float*)d_in[5];
    const float* Wq = (const float*)d_in[6];
    const float* bq = (const float*)d_in[7];
    const float* Wk = (const float*)d_in[8];
    const float* bk = (const float*)d_in[9];
    const float* Wv = (const float*)d_in[10];
    const float* bv = (const float*)d_in[11];
    const float* Ws = (const float*)d_in[12];
    const float* bs = (const float*)d_in[13];
    const float* ow1 = (const float*)d_in[14];
    const float* ob1 = (const float*)d_in[15];
    const float* ow2 = (const float*)d_in[16];
    const float* ob2 = (const float*)d_in[17];
    const float* ow3 = (const float*)d_in[18];
    const float* ob3 = (const float*)d_in[19];
    float* out = (float*)d_out;

    dim3 ggrid((NN+255)/256, 13);

    // ordered so launch index 3 (the one ncu captures) is the layer-0 GEMM
    k_wconv<<<(4*13*4096+255)/256, 256>>>(Wq, Wk, Wv, Ws);          // 0 (+ deg zero)
    k_hist<<<(EE+255)/256, 256>>>(ei);                              // 1
    k_encoder<<<(NN+63)/64, 256>>>(x, enc_w1, enc_b1, enc_w2, enc_b2); // 2
    k_gemm<<<ggrid, 256>>>(0, 0, bq, bk, bv, bs);                   // 3 <- ncu
    k_scan<<<1, 1024>>>();                                          // 4
    k_fill<<<(EE+255)/256, 256>>>(ei);                              // 5
    k_edge<<<(NN*32 + 255)/256, 256>>>(0);                          // 6

    for (int l = 1; l < 4; l++){
        int pp = l & 1;
        k_gemm<<<ggrid, 256>>>(l, pp, bq + l*256, bk + l*256, bv + l*256, bs + l*64);
        k_edge<<<(NN*32 + 255)/256, 256>>>(pp);
    }

    // output MLP (final h is in g_h16 after layer 3)
    k_out<<<(NN+31)/32, 256>>>(ow1, ob1, ow2, ob2, ow3, ob3, out);
}

// round 15
// speedup vs baseline: 1.0876x; 1.0388x over previous
#include <cuda_runtime.h>
#include <cuda_bf16.h>
#include <cuda_fp16.h>
#include <cstdint>

#define NN 50000
#define EE 500000

// ---------------- device scratch (no allocs allowed) ----------------
__device__ __align__(16) __half g_h16 [NN*64];
__device__ __align__(16) __half g_hn16[NN*64];
__device__ __align__(16) __half g_q16[NN*256];
__device__ __align__(16) __half g_kv [NN*512];   // per node: k[0,256), v[256,512)
__device__ __align__(16) __half g_s16[NN*64];
__device__ __align__(16) __half g_w16[4*13*4096]; // fp16 weights [l][t][n][k]
__device__ int   g_deg[NN];
__device__ int   g_rowptr[NN+1];
__device__ int   g_cursor[NN];
__device__ int   g_srcs[EE];

__device__ __forceinline__ float elu(float x){ return x > 0.f ? x : (__expf(x) - 1.f); }

__device__ __forceinline__ void mma_f16(float* d, const uint32_t* a, uint32_t b0, uint32_t b1){
    asm volatile("mma.sync.aligned.m16n8k16.row.col.f32.f16.f16.f32 "
        "{%0,%1,%2,%3}, {%4,%5,%6,%7}, {%8,%9}, {%0,%1,%2,%3};"
        : "+f"(d[0]), "+f"(d[1]), "+f"(d[2]), "+f"(d[3])
        : "r"(a[0]), "r"(a[1]), "r"(a[2]), "r"(a[3]), "r"(b0), "r"(b1));
}

__device__ __forceinline__ void ldsm_x4(uint32_t* r, uint32_t addr){
    asm volatile("ldmatrix.sync.aligned.m8n8.x4.shared.b16 {%0,%1,%2,%3}, [%4];"
        : "=r"(r[0]), "=r"(r[1]), "=r"(r[2]), "=r"(r[3]) : "r"(addr));
}

__device__ __forceinline__ uint32_t smem_u32(const void* p){
    return (uint32_t)__cvta_generic_to_shared(p);
}

// ---------------- weight pre-conversion ----------------
__global__ void k_wconv(const float* __restrict__ Wq, const float* __restrict__ Wk,
                        const float* __restrict__ Wv, const float* __restrict__ Ws){
    int idx = blockIdx.x*blockDim.x + threadIdx.x;   // over 4*13*4096
    if (idx >= 4*13*4096) return;
    int l = idx / (13*4096);
    int r = idx % (13*4096);
    int t = r / 4096;
    int i = r % 4096;
    float v;
    if (t < 4)       v = Wq[l*16384 + t*4096 + i];
    else if (t < 8)  v = Wk[l*16384 + (t-4)*4096 + i];
    else if (t < 12) v = Wv[l*16384 + (t-8)*4096 + i];
    else             v = Ws[l*4096 + i];
    g_w16[idx] = __float2half(v);
}

// ---------------- CSR build ----------------
__global__ void k_zero_deg(){
    int i = blockIdx.x*blockDim.x + threadIdx.x;
    if (i < NN) g_deg[i] = 0;
}

__global__ void k_hist(const int* __restrict__ ei){
    int e = blockIdx.x*blockDim.x + threadIdx.x;
    if (e < EE) atomicAdd(&g_deg[ei[EE + e]], 1);
}

// coalesced barrier-round scan (proven in the 590us config)
__global__ void k_scan(){
    __shared__ int wexc[32], wtot[32];
    __shared__ int s_off;
    int tid = threadIdx.x, lane = tid & 31, wid = tid >> 5;
    if (tid == 0) s_off = 0;
    __syncthreads();
    for (int base = 0; base < NN; base += 1024){
        int i = base + tid;
        int v = (i < NN) ? g_deg[i] : 0;
        int incl = v;
        #pragma unroll
        for (int d = 1; d < 32; d <<= 1){
            int t = __shfl_up_sync(0xffffffffu, incl, d);
            if (lane >= d) incl += t;
        }
        if (lane == 31) wtot[wid] = incl;
        __syncthreads();
        if (wid == 0){
            int wv = wtot[lane];
            int wi = wv;
            #pragma unroll
            for (int d = 1; d < 32; d <<= 1){
                int t = __shfl_up_sync(0xffffffffu, wi, d);
                if (lane >= d) wi += t;
            }
            wexc[lane] = wi - wv;
        }
        __syncthreads();
        int excl = s_off + wexc[wid] + incl - v;
        if (i < NN){ g_rowptr[i] = excl; g_cursor[i] = excl; }
        __syncthreads();
        if (tid == 0) s_off += wexc[31] + wtot[31];
        __syncthreads();
    }
    if (tid == 0) g_rowptr[NN] = s_off;
}

__global__ void k_fill(const int* __restrict__ ei){
    int e = blockIdx.x*blockDim.x + threadIdx.x;
    if (e < EE){
        int d = ei[EE + e];
        int p = atomicAdd(&g_cursor[d], 1);
        g_srcs[p] = ei[e];
    }
}

// ---------------- encoder: x(N,8) -> h(N,64), two ELU linears ----------------
__global__ void k_encoder(const float* __restrict__ x,
                          const float* __restrict__ w1, const float* __restrict__ b1,
                          const float* __restrict__ w2, const float* __restrict__ b2){
    __shared__ float sw1[8*64];    // [k][u]
    __shared__ float sw2[64*64];   // [k][u]
    __shared__ float sb1[64], sb2[64];
    __shared__ float st1[4][64];
    int tid = threadIdx.x;
    #pragma unroll
    for (int i = 0; i < 2; i++){
        int idx = tid + i*256;
        int u = idx >> 3, k = idx & 7;
        sw1[k*64 + u] = w1[idx];
    }
    #pragma unroll
    for (int i = 0; i < 16; i++){
        int idx = tid + i*256;
        sw2[(idx & 63)*64 + (idx >> 6)] = w2[idx];
    }
    if (tid < 64){ sb1[tid] = b1[tid]; sb2[tid] = b2[tid]; }
    __syncthreads();

    int u = tid & 63, nl = tid >> 6;
    int n0 = blockIdx.x * 64;
    for (int it = 0; it < 16; ++it){
        int n = n0 + it*4 + nl;
        float t1 = 0.f;
        if (n < NN){
            float s = sb1[u];
            #pragma unroll
            for (int k = 0; k < 8; k++) s += x[n*8 + k] * sw1[k*64 + u];
            t1 = elu(s);
        }
        st1[nl][u] = t1;
        __syncthreads();
        if (n < NN){
            float s = sb2[u];
            #pragma unroll
            for (int k = 0; k < 64; k++) s += st1[nl][k] * sw2[k*64 + u];
            g_h16[n*64 + u] = __float2half(elu(s));
        }
        __syncthreads();
    }
}

// ---------------- per-layer q/k/v/skip GEMM: fp16 mma m16n8k16 + ldmatrix ----------------
// 128-row M-tiles (proven 35.2us config), staged smem epilogue.
__global__ __launch_bounds__(256) void k_gemm(int layer, int pp,
                       const float* __restrict__ bq, const float* __restrict__ bk,
                       const float* __restrict__ bv, const float* __restrict__ bs){
    const __half* hin = pp ? g_hn16 : g_h16;
    int t = blockIdx.y;
    const __half* W = &g_w16[(layer*13 + t)*4096];
    const float* bias; __half* out; int ldo, coff;
    if (t < 4)      { bias = bq + t*64;      out = g_q16; ldo = 256; coff = t*64; }
    else if (t < 8) { bias = bk + (t-4)*64;  out = g_kv;  ldo = 512; coff = (t-4)*64; }
    else if (t <12) { bias = bv + (t-8)*64;  out = g_kv;  ldo = 512; coff = 256 + (t-8)*64; }
    else            { bias = bs;             out = g_s16; ldo = 64;  coff = 0; }

    __shared__ uint32_t sA[128*36];
    __shared__ uint32_t sB[64*36];
    int tid = threadIdx.x;
    int m0 = blockIdx.x * 128;

    #pragma unroll
    for (int i = 0; i < 4; i++){
        int idx = tid + i*256;
        int row = idx >> 3;
        int c8  = idx & 7;
        uint4 va = make_uint4(0,0,0,0);
        if (m0 + row < NN) va = *(const uint4*)&hin[(m0 + row)*64 + c8*8];
        *(uint4*)&sA[row*36 + c8*4] = va;
    }
    #pragma unroll
    for (int i = 0; i < 2; i++){
        int idx = tid + i*256;
        int row = idx >> 3;
        int c8  = idx & 7;
        uint4 vb = *(const uint4*)&W[row*64 + c8*8];
        *(uint4*)&sB[row*36 + c8*4] = vb;
    }
    __syncthreads();

    int wid = tid >> 5, lane = tid & 31;
    int g = lane >> 2, t4 = lane & 3;
    int wr = wid * 16;

    uint32_t aBase = smem_u32(sA) + (((wr + (lane & 15))*36 + ((lane & 16) ? 4 : 0)) << 2);
    uint32_t bBase = smem_u32(sB) + (((((lane >> 4) & 1)*8 + (lane & 7))*36 + ((lane >> 3) & 1)*4) << 2);

    float acc[8][4] = {};

    #pragma unroll
    for (int kc = 0; kc < 4; kc++){
        uint32_t a[4];
        ldsm_x4(a, aBase + kc*32);
        #pragma unroll
        for (int nt2 = 0; nt2 < 8; nt2 += 2){
            uint32_t b[4];
            ldsm_x4(b, bBase + nt2*1152 + kc*32);
            mma_f16(acc[nt2],   a, b[0], b[1]);
            mma_f16(acc[nt2+1], a, b[2], b[3]);
        }
    }

    // staged epilogue: regs -> smem (conflict-free) -> coalesced uint4 stores
    __syncthreads();
    __half* sOut = (__half*)sA;
    {
        int r0 = wr + g;
        #pragma unroll
        for (int nt = 0; nt < 8; nt++){
            int col = nt*8 + t4*2;
            float bz0 = bias[col], bz1 = bias[col+1];
            *(__half2*)&sOut[r0*72 + col]     = __floats2half2_rn(acc[nt][0] + bz0, acc[nt][1] + bz1);
            *(__half2*)&sOut[(r0+8)*72 + col] = __floats2half2_rn(acc[nt][2] + bz0, acc[nt][3] + bz1);
        }
    }
    __syncthreads();
    #pragma unroll
    for (int i = 0; i < 4; i++){
        int idx = tid + i*256;
        int row = idx >> 3;
        int c8  = idx & 7;
        if (m0 + row < NN)
            *(uint4*)&out[(m0 + row)*ldo + coff + c8*8] = *(uint4*)&sOut[row*72 + c8*8];
    }
}

// ---------------- edge kernel: per-dst warp, independent-edge softmax ----------------
__global__ void k_edge(int pp){
    int gw = (blockIdx.x*blockDim.x + threadIdx.x) >> 5;
    int lane = threadIdx.x & 31;
    if (gw >= NN) return;
    int dst = gw;
    __half* hout = pp ? g_h16 : g_hn16;

    uint4 qr = *(const uint4*)&g_q16[dst*256 + lane*8];
    __half2 sc = __float2half2_rn(0.125f);
    __half2 qh0 = __hmul2(*(__half2*)&qr.x, sc);
    __half2 qh1 = __hmul2(*(__half2*)&qr.y, sc);
    __half2 qh2 = __hmul2(*(__half2*)&qr.z, sc);
    __half2 qh3 = __hmul2(*(__half2*)&qr.w, sc);

    int beg = g_rowptr[dst], end = g_rowptr[dst+1];

    float ssum = 0.f;
    float acc[8] = {0,0,0,0,0,0,0,0};

    #pragma unroll 8
    for (int p = beg; p < end; p++){
        int s = g_srcs[p];
        uint4 kr = *(const uint4*)&g_kv[s*512 + lane*8];
        uint4 vr = *(const uint4*)&g_kv[s*512 + 256 + lane*8];
        __half2 d2 = __hmul2(qh0, *(__half2*)&kr.x);
        d2 = __hfma2(qh1, *(__half2*)&kr.y, d2);
        d2 = __hfma2(qh2, *(__half2*)&kr.z, d2);
        d2 = __hfma2(qh3, *(__half2*)&kr.w, d2);
        float2 df = __half22float2(d2);
        float d = df.x + df.y;
        d += __shfl_xor_sync(0xffffffffu, d, 1);
        d += __shfl_xor_sync(0xffffffffu, d, 2);
        d += __shfl_xor_sync(0xffffffffu, d, 4);
        float e = __expf(d);
        ssum += e;
        float2 v0 = __half22float2(*(__half2*)&vr.x);
        float2 v1 = __half22float2(*(__half2*)&vr.y);
        float2 v2 = __half22float2(*(__half2*)&vr.z);
        float2 v3 = __half22float2(*(__half2*)&vr.w);
        acc[0] += e*v0.x; acc[1] += e*v0.y;
        acc[2] += e*v1.x; acc[3] += e*v1.y;
        acc[4] += e*v2.x; acc[5] += e*v2.y;
        acc[6] += e*v3.x; acc[7] += e*v3.y;
    }

    float inv = (end > beg) ? 1.f / ssum : 0.f;
    #pragma unroll
    for (int j = 0; j < 8; j++){
        float aj = acc[j] * inv;
        aj += __shfl_xor_sync(0xffffffffu, aj, 8);
        aj += __shfl_xor_sync(0xffffffffu, aj, 16);
        acc[j] = aj;
    }
    if (lane < 8){
        // vectorized epilogue: one uint4 skip-load + one uint4 h-store per lane
        uint4 sr = *(const uint4*)&g_s16[dst*64 + lane*8];
        float2 s0 = __half22float2(*(__half2*)&sr.x);
        float2 s1 = __half22float2(*(__half2*)&sr.y);
        float2 s2 = __half22float2(*(__half2*)&sr.z);
        float2 s3 = __half22float2(*(__half2*)&sr.w);
        float o0 = elu(acc[0]*0.25f + s0.x), o1 = elu(acc[1]*0.25f + s0.y);
        float o2 = elu(acc[2]*0.25f + s1.x), o3 = elu(acc[3]*0.25f + s1.y);
        float o4 = elu(acc[4]*0.25f + s2.x), o5 = elu(acc[5]*0.25f + s2.y);
        float o6 = elu(acc[6]*0.25f + s3.x), o7 = elu(acc[7]*0.25f + s3.y);
        uint4 hw;
        *(__half2*)&hw.x = __floats2half2_rn(o0, o1);
        *(__half2*)&hw.y = __floats2half2_rn(o2, o3);
        *(__half2*)&hw.z = __floats2half2_rn(o4, o5);
        *(__half2*)&hw.w = __floats2half2_rn(o6, o7);
        *(uint4*)&hout[dst*64 + lane*8] = hw;
    }
}

// ---------------- output MLP: 64 -> 64 -> 32 -> 8 ----------------
__global__ void k_out(const float* __restrict__ w1, const float* __restrict__ b1,
                      const float* __restrict__ w2, const float* __restrict__ b2,
                      const float* __restrict__ w3, const float* __restrict__ b3,
                      float* __restrict__ out){
    __shared__ float sw1[64*64];
    __shared__ float sw2[64*32];
    __shared__ float sw3[32*8];
    __shared__ float sb1[64], sb2[32], sb3[8];
    __shared__ float so1[4][64];
    __shared__ float so2[4][32];
    int tid = threadIdx.x;
    #pragma unroll
    for (int i = 0; i < 16; i++){
        int idx = tid + i*256;
        sw1[(idx & 63)*64 + (idx >> 6)] = w1[idx];
    }
    #pragma unroll
    for (int i = 0; i < 8; i++){
        int idx = tid + i*256;
        sw2[(idx & 63)*32 + (idx >> 6)] = w2[idx];
    }
    { int idx = tid;
      sw3[(idx & 31)*8 + (idx >> 5)] = w3[idx]; }
    if (tid < 64) sb1[tid] = b1[tid];
    if (tid < 32) sb2[tid] = b2[tid];
    if (tid < 8)  sb3[tid] = b3[tid];
    __syncthreads();

    int u = tid & 63, nl = tid >> 6;
    int n0 = blockIdx.x * 32;
    for (int it = 0; it < 8; ++it){
        int n = n0 + it*4 + nl;
        float o1v = 0.f;
        if (n < NN){
            float s = sb1[u];
            #pragma unroll
            for (int k = 0; k < 64; k++) s += __half2float(g_h16[n*64 + k]) * sw1[k*64 + u];
            o1v = elu(s);
        }
        so1[nl][u] = o1v;
        __syncthreads();
        if (u < 32 && n < NN){
            float s = sb2[u];
            #pragma unroll
            for (int k = 0; k < 64; k++) s += so1[nl][k] * sw2[k*32 + u];
            so2[nl][u] = elu(s);
        }
        __syncthreads();
        if (u < 8 && n < NN){
            float s = sb3[u];
            #pragma unroll
            for (int k = 0; k < 32; k++) s += so2[nl][k] * sw3[k*8 + u];
            out[n*8 + u] = s;
        }
        __syncthreads();
    }
}

// ---------------- launch ----------------
extern "C" void kernel_launch(void* const* d_in, const int* in_sizes, int n_in,
                              void* d_out, int out_size){
    const float* x   = (const float*)d_in[0];
    const int*   ei  = (const int*)d_in[1];
    const float* enc_w1 = (const float*)d_in[2];
    const float* enc_b1 = (const float*)d_in[3];
    const float* enc_w2 = (const float*)d_in[4];
    const float* enc_b2 = (const float*)d_in[5];
    const float* Wq = (const float*)d_in[6];
    const float* bq = (const float*)d_in[7];
    const float* Wk = (const float*)d_in[8];
    const float* bk = (const float*)d_in[9];
    const float* Wv = (const float*)d_in[10];
    const float* bv = (const float*)d_in[11];
    const float* Ws = (const float*)d_in[12];
    const float* bs = (const float*)d_in[13];
    const float* ow1 = (const float*)d_in[14];
    const float* ob1 = (const float*)d_in[15];
    const float* ow2 = (const float*)d_in[16];
    const float* ob2 = (const float*)d_in[17];
    const float* ow3 = (const float*)d_in[18];
    const float* ob3 = (const float*)d_in[19];
    float* out = (float*)d_out;

    dim3 ggrid((NN+127)/128, 13);

    // launch order matches the proven 589.9us configuration
    k_wconv<<<(4*13*4096+255)/256, 256>>>(Wq, Wk, Wv, Ws);          // 0
    k_encoder<<<(NN+63)/64, 256>>>(x, enc_w1, enc_b1, enc_w2, enc_b2); // 1
    k_zero_deg<<<(NN+255)/256, 256>>>();                            // 2
    k_gemm<<<ggrid, 256>>>(0, 0, bq, bk, bv, bs);                   // 3 <- ncu
    k_hist<<<(EE+255)/256, 256>>>(ei);                              // 4
    k_scan<<<1, 1024>>>();                                          // 5
    k_fill<<<(EE+255)/256, 256>>>(ei);                              // 6
    k_edge<<<(NN*32 + 255)/256, 256>>>(0);                          // 7

    for (int l = 1; l < 4; l++){
        int pp = l & 1;
        k_gemm<<<ggrid, 256>>>(l, pp, bq + l*256, bk + l*256, bv + l*256, bs + l*64);
        k_edge<<<(NN*32 + 255)/256, 256>>>(pp);
    }

    // output MLP (final h is in g_h16 after layer 3)
    k_out<<<(NN+31)/32, 256>>>(ow1, ob1, ow2, ob2, ow3, ob3, out);
}

// round 16
// speedup vs baseline: 1.1202x; 1.0300x over previous
#include <cuda_runtime.h>
#include <cuda_bf16.h>
#include <cuda_fp16.h>
#include <cstdint>

#define NN 50000
#define EE 500000

// ---------------- device scratch (no allocs allowed) ----------------
__device__ __align__(16) __half g_h16 [NN*64];
__device__ __align__(16) __half g_hn16[NN*64];
__device__ __align__(16) __half g_q16[NN*256];
__device__ __align__(16) __half g_kv [NN*512];   // per node: k[0,256), v[256,512)
__device__ __align__(16) __half g_s16[NN*64];
__device__ __align__(16) __half g_w16[4*13*4096]; // fp16 weights [l][t][n][k]
__device__ int   g_deg[NN];
__device__ int   g_rowptr[NN+1];
__device__ int   g_cursor[NN];
__device__ int   g_srcs[EE];

__device__ __forceinline__ float elu(float x){ return x > 0.f ? x : (__expf(x) - 1.f); }

__device__ __forceinline__ void mma_f16(float* d, const uint32_t* a, uint32_t b0, uint32_t b1){
    asm volatile("mma.sync.aligned.m16n8k16.row.col.f32.f16.f16.f32 "
        "{%0,%1,%2,%3}, {%4,%5,%6,%7}, {%8,%9}, {%0,%1,%2,%3};"
        : "+f"(d[0]), "+f"(d[1]), "+f"(d[2]), "+f"(d[3])
        : "r"(a[0]), "r"(a[1]), "r"(a[2]), "r"(a[3]), "r"(b0), "r"(b1));
}

__device__ __forceinline__ void ldsm_x4(uint32_t* r, uint32_t addr){
    asm volatile("ldmatrix.sync.aligned.m8n8.x4.shared.b16 {%0,%1,%2,%3}, [%4];"
        : "=r"(r[0]), "=r"(r[1]), "=r"(r[2]), "=r"(r[3]) : "r"(addr));
}

__device__ __forceinline__ uint32_t smem_u32(const void* p){
    return (uint32_t)__cvta_generic_to_shared(p);
}

// ---------------- weight pre-conversion ----------------
__global__ void k_wconv(const float* __restrict__ Wq, const float* __restrict__ Wk,
                        const float* __restrict__ Wv, const float* __restrict__ Ws){
    int idx = blockIdx.x*blockDim.x + threadIdx.x;   // over 4*13*4096
    if (idx >= 4*13*4096) return;
    int l = idx / (13*4096);
    int r = idx % (13*4096);
    int t = r / 4096;
    int i = r % 4096;
    float v;
    if (t < 4)       v = Wq[l*16384 + t*4096 + i];
    else if (t < 8)  v = Wk[l*16384 + (t-4)*4096 + i];
    else if (t < 12) v = Wv[l*16384 + (t-8)*4096 + i];
    else             v = Ws[l*4096 + i];
    g_w16[idx] = __float2half(v);
}

// ---------------- CSR build ----------------
__global__ void k_zero_deg(){
    int i = blockIdx.x*blockDim.x + threadIdx.x;
    if (i < NN) g_deg[i] = 0;
}

__global__ void k_hist(const int* __restrict__ ei){
    int e = blockIdx.x*blockDim.x + threadIdx.x;
    if (e < EE) atomicAdd(&g_deg[ei[EE + e]], 1);
}

// coalesced barrier-round scan (proven)
__global__ void k_scan(){
    __shared__ int wexc[32], wtot[32];
    __shared__ int s_off;
    int tid = threadIdx.x, lane = tid & 31, wid = tid >> 5;
    if (tid == 0) s_off = 0;
    __syncthreads();
    for (int base = 0; base < NN; base += 1024){
        int i = base + tid;
        int v = (i < NN) ? g_deg[i] : 0;
        int incl = v;
        #pragma unroll
        for (int d = 1; d < 32; d <<= 1){
            int t = __shfl_up_sync(0xffffffffu, incl, d);
            if (lane >= d) incl += t;
        }
        if (lane == 31) wtot[wid] = incl;
        __syncthreads();
        if (wid == 0){
            int wv = wtot[lane];
            int wi = wv;
            #pragma unroll
            for (int d = 1; d < 32; d <<= 1){
                int t = __shfl_up_sync(0xffffffffu, wi, d);
                if (lane >= d) wi += t;
            }
            wexc[lane] = wi - wv;
        }
        __syncthreads();
        int excl = s_off + wexc[wid] + incl - v;
        if (i < NN){ g_rowptr[i] = excl; g_cursor[i] = excl; }
        __syncthreads();
        if (tid == 0) s_off += wexc[31] + wtot[31];
        __syncthreads();
    }
    if (tid == 0) g_rowptr[NN] = s_off;
}

__global__ void k_fill(const int* __restrict__ ei){
    int e = blockIdx.x*blockDim.x + threadIdx.x;
    if (e < EE){
        int d = ei[EE + e];
        int p = atomicAdd(&g_cursor[d], 1);
        g_srcs[p] = ei[e];
    }
}

// ---------------- encoder: x(N,8) -> h(N,64), two ELU linears ----------------
__global__ void k_encoder(const float* __restrict__ x,
                          const float* __restrict__ w1, const float* __restrict__ b1,
                          const float* __restrict__ w2, const float* __restrict__ b2){
    __shared__ float sw1[8*64];    // [k][u]
    __shared__ float sw2[64*64];   // [k][u]
    __shared__ float sb1[64], sb2[64];
    __shared__ float st1[4][64];
    int tid = threadIdx.x;
    #pragma unroll
    for (int i = 0; i < 2; i++){
        int idx = tid + i*256;
        int u = idx >> 3, k = idx & 7;
        sw1[k*64 + u] = w1[idx];
    }
    #pragma unroll
    for (int i = 0; i < 16; i++){
        int idx = tid + i*256;
        sw2[(idx & 63)*64 + (idx >> 6)] = w2[idx];
    }
    if (tid < 64){ sb1[tid] = b1[tid]; sb2[tid] = b2[tid]; }
    __syncthreads();

    int u = tid & 63, nl = tid >> 6;
    int n0 = blockIdx.x * 64;
    for (int it = 0; it < 16; ++it){
        int n = n0 + it*4 + nl;
        float t1 = 0.f;
        if (n < NN){
            float s = sb1[u];
            #pragma unroll
            for (int k = 0; k < 8; k++) s += x[n*8 + k] * sw1[k*64 + u];
            t1 = elu(s);
        }
        st1[nl][u] = t1;
        __syncthreads();
        if (n < NN){
            float s = sb2[u];
            #pragma unroll
            for (int k = 0; k < 64; k++) s += st1[nl][k] * sw2[k*64 + u];
            g_h16[n*64 + u] = __float2half(elu(s));
        }
        __syncthreads();
    }
}

// ---------------- per-layer q/k/v/skip GEMM: fp16 mma m16n8k16 + ldmatrix ----------------
// 128-row M-tiles (proven 35.2us config), staged smem epilogue.
__global__ __launch_bounds__(256) void k_gemm(int layer, int pp,
                       const float* __restrict__ bq, const float* __restrict__ bk,
                       const float* __restrict__ bv, const float* __restrict__ bs){
    const __half* hin = pp ? g_hn16 : g_h16;
    int t = blockIdx.y;
    const __half* W = &g_w16[(layer*13 + t)*4096];
    const float* bias; __half* out; int ldo, coff;
    if (t < 4)      { bias = bq + t*64;      out = g_q16; ldo = 256; coff = t*64; }
    else if (t < 8) { bias = bk + (t-4)*64;  out = g_kv;  ldo = 512; coff = (t-4)*64; }
    else if (t <12) { bias = bv + (t-8)*64;  out = g_kv;  ldo = 512; coff = 256 + (t-8)*64; }
    else            { bias = bs;             out = g_s16; ldo = 64;  coff = 0; }

    __shared__ uint32_t sA[128*36];
    __shared__ uint32_t sB[64*36];
    int tid = threadIdx.x;
    int m0 = blockIdx.x * 128;

    #pragma unroll
    for (int i = 0; i < 4; i++){
        int idx = tid + i*256;
        int row = idx >> 3;
        int c8  = idx & 7;
        uint4 va = make_uint4(0,0,0,0);
        if (m0 + row < NN) va = *(const uint4*)&hin[(m0 + row)*64 + c8*8];
        *(uint4*)&sA[row*36 + c8*4] = va;
    }
    #pragma unroll
    for (int i = 0; i < 2; i++){
        int idx = tid + i*256;
        int row = idx >> 3;
        int c8  = idx & 7;
        uint4 vb = *(const uint4*)&W[row*64 + c8*8];
        *(uint4*)&sB[row*36 + c8*4] = vb;
    }
    __syncthreads();

    int wid = tid >> 5, lane = tid & 31;
    int g = lane >> 2, t4 = lane & 3;
    int wr = wid * 16;

    uint32_t aBase = smem_u32(sA) + (((wr + (lane & 15))*36 + ((lane & 16) ? 4 : 0)) << 2);
    uint32_t bBase = smem_u32(sB) + (((((lane >> 4) & 1)*8 + (lane & 7))*36 + ((lane >> 3) & 1)*4) << 2);

    float acc[8][4] = {};

    #pragma unroll
    for (int kc = 0; kc < 4; kc++){
        uint32_t a[4];
        ldsm_x4(a, aBase + kc*32);
        #pragma unroll
        for (int nt2 = 0; nt2 < 8; nt2 += 2){
            uint32_t b[4];
            ldsm_x4(b, bBase + nt2*1152 + kc*32);
            mma_f16(acc[nt2],   a, b[0], b[1]);
            mma_f16(acc[nt2+1], a, b[2], b[3]);
        }
    }

    // staged epilogue: regs -> smem (conflict-free) -> coalesced uint4 stores
    __syncthreads();
    __half* sOut = (__half*)sA;
    {
        int r0 = wr + g;
        #pragma unroll
        for (int nt = 0; nt < 8; nt++){
            int col = nt*8 + t4*2;
            float bz0 = bias[col], bz1 = bias[col+1];
            *(__half2*)&sOut[r0*72 + col]     = __floats2half2_rn(acc[nt][0] + bz0, acc[nt][1] + bz1);
            *(__half2*)&sOut[(r0+8)*72 + col] = __floats2half2_rn(acc[nt][2] + bz0, acc[nt][3] + bz1);
        }
    }
    __syncthreads();
    #pragma unroll
    for (int i = 0; i < 4; i++){
        int idx = tid + i*256;
        int row = idx >> 3;
        int c8  = idx & 7;
        if (m0 + row < NN)
            *(uint4*)&out[(m0 + row)*ldo + coff + c8*8] = *(uint4*)&sOut[row*72 + c8*8];
    }
}

// ---------------- edge kernel: per-dst warp, src-prefetch + shfl broadcast ----------------
// The CSR src list for a dst is contiguous: one coalesced 32-wide load per
// chunk fetches up to 32 indices; __shfl broadcasts them. kv gathers then
// have NO memory-dependent prologue -> full unroll-window of loads in flight.
__global__ void k_edge(int pp){
    int gw = (blockIdx.x*blockDim.x + threadIdx.x) >> 5;
    int lane = threadIdx.x & 31;
    if (gw >= NN) return;
    int dst = gw;
    __half* hout = pp ? g_h16 : g_hn16;

    uint4 qr = *(const uint4*)&g_q16[dst*256 + lane*8];
    __half2 sc = __float2half2_rn(0.125f);
    __half2 qh0 = __hmul2(*(__half2*)&qr.x, sc);
    __half2 qh1 = __hmul2(*(__half2*)&qr.y, sc);
    __half2 qh2 = __hmul2(*(__half2*)&qr.z, sc);
    __half2 qh3 = __hmul2(*(__half2*)&qr.w, sc);

    int beg = g_rowptr[dst], end = g_rowptr[dst+1];

    float ssum = 0.f;
    float acc[8] = {0,0,0,0,0,0,0,0};

    for (int p0 = beg; p0 < end; p0 += 32){
        int cnt = end - p0; if (cnt > 32) cnt = 32;
        int myS = (p0 + lane < end) ? g_srcs[p0 + lane] : 0;

        #pragma unroll 8
        for (int j = 0; j < cnt; j++){
            int s = __shfl_sync(0xffffffffu, myS, j);
            uint4 kr = *(const uint4*)&g_kv[s*512 + lane*8];
            uint4 vr = *(const uint4*)&g_kv[s*512 + 256 + lane*8];
            __half2 d2 = __hmul2(qh0, *(__half2*)&kr.x);
            d2 = __hfma2(qh1, *(__half2*)&kr.y, d2);
            d2 = __hfma2(qh2, *(__half2*)&kr.z, d2);
            d2 = __hfma2(qh3, *(__half2*)&kr.w, d2);
            float2 df = __half22float2(d2);
            float d = df.x + df.y;
            d += __shfl_xor_sync(0xffffffffu, d, 1);
            d += __shfl_xor_sync(0xffffffffu, d, 2);
            d += __shfl_xor_sync(0xffffffffu, d, 4);
            float e = __expf(d);
            ssum += e;
            float2 v0 = __half22float2(*(__half2*)&vr.x);
            float2 v1 = __half22float2(*(__half2*)&vr.y);
            float2 v2 = __half22float2(*(__half2*)&vr.z);
            float2 v3 = __half22float2(*(__half2*)&vr.w);
            acc[0] += e*v0.x; acc[1] += e*v0.y;
            acc[2] += e*v1.x; acc[3] += e*v1.y;
            acc[4] += e*v2.x; acc[5] += e*v2.y;
            acc[6] += e*v3.x; acc[7] += e*v3.y;
        }
    }

    float inv = (end > beg) ? 1.f / ssum : 0.f;
    #pragma unroll
    for (int j = 0; j < 8; j++){
        float aj = acc[j] * inv;
        aj += __shfl_xor_sync(0xffffffffu, aj, 8);
        aj += __shfl_xor_sync(0xffffffffu, aj, 16);
        acc[j] = aj;
    }
    if (lane < 8){
        uint4 sr = *(const uint4*)&g_s16[dst*64 + lane*8];
        float2 s0 = __half22float2(*(__half2*)&sr.x);
        float2 s1 = __half22float2(*(__half2*)&sr.y);
        float2 s2 = __half22float2(*(__half2*)&sr.z);
        float2 s3 = __half22float2(*(__half2*)&sr.w);
        float o0 = elu(acc[0]*0.25f + s0.x), o1 = elu(acc[1]*0.25f + s0.y);
        float o2 = elu(acc[2]*0.25f + s1.x), o3 = elu(acc[3]*0.25f + s1.y);
        float o4 = elu(acc[4]*0.25f + s2.x), o5 = elu(acc[5]*0.25f + s2.y);
        float o6 = elu(acc[6]*0.25f + s3.x), o7 = elu(acc[7]*0.25f + s3.y);
        uint4 hw;
        *(__half2*)&hw.x = __floats2half2_rn(o0, o1);
        *(__half2*)&hw.y = __floats2half2_rn(o2, o3);
        *(__half2*)&hw.z = __floats2half2_rn(o4, o5);
        *(__half2*)&hw.w = __floats2half2_rn(o6, o7);
        *(uint4*)&hout[dst*64 + lane*8] = hw;
    }
}

// ---------------- output MLP: 64 -> 64 -> 32 -> 8 ----------------
__global__ void k_out(const float* __restrict__ w1, const float* __restrict__ b1,
                      const float* __restrict__ w2, const float* __restrict__ b2,
                      const float* __restrict__ w3, const float* __restrict__ b3,
                      float* __restrict__ out){
    __shared__ float sw1[64*64];
    __shared__ float sw2[64*32];
    __shared__ float sw3[32*8];
    __shared__ float sb1[64], sb2[32], sb3[8];
    __shared__ float so1[4][64];
    __shared__ float so2[4][32];
    int tid = threadIdx.x;
    #pragma unroll
    for (int i = 0; i < 16; i++){
        int idx = tid + i*256;
        sw1[(idx & 63)*64 + (idx >> 6)] = w1[idx];
    }
    #pragma unroll
    for (int i = 0; i < 8; i++){
        int idx = tid + i*256;
        sw2[(idx & 63)*32 + (idx >> 6)] = w2[idx];
    }
    { int idx = tid;
      sw3[(idx & 31)*8 + (idx >> 5)] = w3[idx]; }
    if (tid < 64) sb1[tid] = b1[tid];
    if (tid < 32) sb2[tid] = b2[tid];
    if (tid < 8)  sb3[tid] = b3[tid];
    __syncthreads();

    int u = tid & 63, nl = tid >> 6;
    int n0 = blockIdx.x * 32;
    for (int it = 0; it < 8; ++it){
        int n = n0 + it*4 + nl;
        float o1v = 0.f;
        if (n < NN){
            float s = sb1[u];
            #pragma unroll
            for (int k = 0; k < 64; k++) s += __half2float(g_h16[n*64 + k]) * sw1[k*64 + u];
            o1v = elu(s);
        }
        so1[nl][u] = o1v;
        __syncthreads();
        if (u < 32 && n < NN){
            float s = sb2[u];
            #pragma unroll
            for (int k = 0; k < 64; k++) s += so1[nl][k] * sw2[k*32 + u];
            so2[nl][u] = elu(s);
        }
        __syncthreads();
        if (u < 8 && n < NN){
            float s = sb3[u];
            #pragma unroll
            for (int k = 0; k < 32; k++) s += so2[nl][k] * sw3[k*8 + u];
            out[n*8 + u] = s;
        }
        __syncthreads();
    }
}

// ---------------- launch ----------------
extern "C" void kernel_launch(void* const* d_in, const int* in_sizes, int n_in,
                              void* d_out, int out_size){
    const float* x   = (const float*)d_in[0];
    const int*   ei  = (const int*)d_in[1];
    const float* enc_w1 = (const float*)d_in[2];
    const float* enc_b1 = (const float*)d_in[3];
    const float* enc_w2 = (const float*)d_in[4];
    const float* enc_b2 = (const float*)d_in[5];
    const float* Wq = (const float*)d_in[6];
    const float* bq = (const float*)d_in[7];
    const float* Wk = (const float*)d_in[8];
    const float* bk = (const float*)d_in[9];
    const float* Wv = (const float*)d_in[10];
    const float* bv = (const float*)d_in[11];
    const float* Ws = (const float*)d_in[12];
    const float* bs = (const float*)d_in[13];
    const float* ow1 = (const float*)d_in[14];
    const float* ob1 = (const float*)d_in[15];
    const float* ow2 = (const float*)d_in[16];
    const float* ob2 = (const float*)d_in[17];
    const float* ow3 = (const float*)d_in[18];
    const float* ob3 = (const float*)d_in[19];
    float* out = (float*)d_out;

    dim3 ggrid((NN+127)/128, 13);

    // launch order matches the proven 581.7us configuration
    k_wconv<<<(4*13*4096+255)/256, 256>>>(Wq, Wk, Wv, Ws);          // 0
    k_encoder<<<(NN+63)/64, 256>>>(x, enc_w1, enc_b1, enc_w2, enc_b2); // 1
    k_zero_deg<<<(NN+255)/256, 256>>>();                            // 2
    k_gemm<<<ggrid, 256>>>(0, 0, bq, bk, bv, bs);                   // 3 <- ncu
    k_hist<<<(EE+255)/256, 256>>>(ei);                              // 4
    k_scan<<<1, 1024>>>();                                          // 5
    k_fill<<<(EE+255)/256, 256>>>(ei);                              // 6
    k_edge<<<(NN*32 + 255)/256, 256>>>(0);                          // 7

    for (int l = 1; l < 4; l++){
        int pp = l & 1;
        k_gemm<<<ggrid, 256>>>(l, pp, bq + l*256, bk + l*256, bv + l*256, bs + l*64);
        k_edge<<<(NN*32 + 255)/256, 256>>>(pp);
    }

    // output MLP (final h is in g_h16 after layer 3)
    k_out<<<(NN+31)/32, 256>>>(ow1, ob1, ow2, ob2, ow3, ob3, out);
}

// round 17
// speedup vs baseline: 1.1224x; 1.0020x over previous
#include <cuda_runtime.h>
#include <cuda_bf16.h>
#include <cuda_fp16.h>
#include <cstdint>

#define NN 50000
#define EE 500000

// ---------------- device scratch (no allocs allowed) ----------------
__device__ __align__(16) __half g_h16 [NN*64];
__device__ __align__(16) __half g_hn16[NN*64];
__device__ __align__(16) __half g_q16[NN*256];
__device__ __align__(16) __half g_kv [NN*512];   // per node: k[0,256), v[256,512)
__device__ __align__(16) __half g_s16[NN*64];
__device__ __align__(16) __half g_w16[4*13*4096]; // fp16 weights [l][t][n][k]
__device__ int   g_deg[NN];
__device__ int   g_rowptr[NN+1];
__device__ int   g_cursor[NN];
__device__ int   g_srcs[EE];

__device__ __forceinline__ float elu(float x){ return x > 0.f ? x : (__expf(x) - 1.f); }

__device__ __forceinline__ void mma_f16(float* d, const uint32_t* a, uint32_t b0, uint32_t b1){
    asm volatile("mma.sync.aligned.m16n8k16.row.col.f32.f16.f16.f32 "
        "{%0,%1,%2,%3}, {%4,%5,%6,%7}, {%8,%9}, {%0,%1,%2,%3};"
        : "+f"(d[0]), "+f"(d[1]), "+f"(d[2]), "+f"(d[3])
        : "r"(a[0]), "r"(a[1]), "r"(a[2]), "r"(a[3]), "r"(b0), "r"(b1));
}

__device__ __forceinline__ void ldsm_x4(uint32_t* r, uint32_t addr){
    asm volatile("ldmatrix.sync.aligned.m8n8.x4.shared.b16 {%0,%1,%2,%3}, [%4];"
        : "=r"(r[0]), "=r"(r[1]), "=r"(r[2]), "=r"(r[3]) : "r"(addr));
}

__device__ __forceinline__ uint32_t smem_u32(const void* p){
    return (uint32_t)__cvta_generic_to_shared(p);
}

// ---------------- weight pre-conversion ----------------
__global__ void k_wconv(const float* __restrict__ Wq, const float* __restrict__ Wk,
                        const float* __restrict__ Wv, const float* __restrict__ Ws){
    int idx = blockIdx.x*blockDim.x + threadIdx.x;   // over 4*13*4096
    if (idx >= 4*13*4096) return;
    int l = idx / (13*4096);
    int r = idx % (13*4096);
    int t = r / 4096;
    int i = r % 4096;
    float v;
    if (t < 4)       v = Wq[l*16384 + t*4096 + i];
    else if (t < 8)  v = Wk[l*16384 + (t-4)*4096 + i];
    else if (t < 12) v = Wv[l*16384 + (t-8)*4096 + i];
    else             v = Ws[l*4096 + i];
    g_w16[idx] = __float2half(v);
}

// ---------------- CSR build ----------------
__global__ void k_zero_deg(){
    int i = blockIdx.x*blockDim.x + threadIdx.x;
    if (i < NN) g_deg[i] = 0;
}

__global__ void k_hist(const int* __restrict__ ei){
    int e = blockIdx.x*blockDim.x + threadIdx.x;
    if (e < EE) atomicAdd(&g_deg[ei[EE + e]], 1);
}

// coalesced barrier-round scan (proven)
__global__ void k_scan(){
    __shared__ int wexc[32], wtot[32];
    __shared__ int s_off;
    int tid = threadIdx.x, lane = tid & 31, wid = tid >> 5;
    if (tid == 0) s_off = 0;
    __syncthreads();
    for (int base = 0; base < NN; base += 1024){
        int i = base + tid;
        int v = (i < NN) ? g_deg[i] : 0;
        int incl = v;
        #pragma unroll
        for (int d = 1; d < 32; d <<= 1){
            int t = __shfl_up_sync(0xffffffffu, incl, d);
            if (lane >= d) incl += t;
        }
        if (lane == 31) wtot[wid] = incl;
        __syncthreads();
        if (wid == 0){
            int wv = wtot[lane];
            int wi = wv;
            #pragma unroll
            for (int d = 1; d < 32; d <<= 1){
                int t = __shfl_up_sync(0xffffffffu, wi, d);
                if (lane >= d) wi += t;
            }
            wexc[lane] = wi - wv;
        }
        __syncthreads();
        int excl = s_off + wexc[wid] + incl - v;
        if (i < NN){ g_rowptr[i] = excl; g_cursor[i] = excl; }
        __syncthreads();
        if (tid == 0) s_off += wexc[31] + wtot[31];
        __syncthreads();
    }
    if (tid == 0) g_rowptr[NN] = s_off;
}

__global__ void k_fill(const int* __restrict__ ei){
    int e = blockIdx.x*blockDim.x + threadIdx.x;
    if (e < EE){
        int d = ei[EE + e];
        int p = atomicAdd(&g_cursor[d], 1);
        g_srcs[p] = ei[e];
    }
}

// ---------------- encoder: x(N,8) -> h(N,64), two ELU linears ----------------
__global__ void k_encoder(const float* __restrict__ x,
                          const float* __restrict__ w1, const float* __restrict__ b1,
                          const float* __restrict__ w2, const float* __restrict__ b2){
    __shared__ float sw1[8*64];    // [k][u]
    __shared__ float sw2[64*64];   // [k][u]
    __shared__ float sb1[64], sb2[64];
    __shared__ float st1[4][64];
    int tid = threadIdx.x;
    #pragma unroll
    for (int i = 0; i < 2; i++){
        int idx = tid + i*256;
        int u = idx >> 3, k = idx & 7;
        sw1[k*64 + u] = w1[idx];
    }
    #pragma unroll
    for (int i = 0; i < 16; i++){
        int idx = tid + i*256;
        sw2[(idx & 63)*64 + (idx >> 6)] = w2[idx];
    }
    if (tid < 64){ sb1[tid] = b1[tid]; sb2[tid] = b2[tid]; }
    __syncthreads();

    int u = tid & 63, nl = tid >> 6;
    int n0 = blockIdx.x * 64;
    for (int it = 0; it < 16; ++it){
        int n = n0 + it*4 + nl;
        float t1 = 0.f;
        if (n < NN){
            float s = sb1[u];
            #pragma unroll
            for (int k = 0; k < 8; k++) s += x[n*8 + k] * sw1[k*64 + u];
            t1 = elu(s);
        }
        st1[nl][u] = t1;
        __syncthreads();
        if (n < NN){
            float s = sb2[u];
            #pragma unroll
            for (int k = 0; k < 64; k++) s += st1[nl][k] * sw2[k*64 + u];
            g_h16[n*64 + u] = __float2half(elu(s));
        }
        __syncthreads();
    }
}

// ---------------- per-layer q/k/v/skip GEMM: fp16 mma m16n8k16 + ldmatrix ----------------
// 128-row M-tiles (proven 35.2us config), staged smem epilogue.
__global__ __launch_bounds__(256) void k_gemm(int layer, int pp,
                       const float* __restrict__ bq, const float* __restrict__ bk,
                       const float* __restrict__ bv, const float* __restrict__ bs){
    const __half* hin = pp ? g_hn16 : g_h16;
    int t = blockIdx.y;
    const __half* W = &g_w16[(layer*13 + t)*4096];
    const float* bias; __half* out; int ldo, coff;
    if (t < 4)      { bias = bq + t*64;      out = g_q16; ldo = 256; coff = t*64; }
    else if (t < 8) { bias = bk + (t-4)*64;  out = g_kv;  ldo = 512; coff = (t-4)*64; }
    else if (t <12) { bias = bv + (t-8)*64;  out = g_kv;  ldo = 512; coff = 256 + (t-8)*64; }
    else            { bias = bs;             out = g_s16; ldo = 64;  coff = 0; }

    __shared__ uint32_t sA[128*36];
    __shared__ uint32_t sB[64*36];
    int tid = threadIdx.x;
    int m0 = blockIdx.x * 128;

    #pragma unroll
    for (int i = 0; i < 4; i++){
        int idx = tid + i*256;
        int row = idx >> 3;
        int c8  = idx & 7;
        uint4 va = make_uint4(0,0,0,0);
        if (m0 + row < NN) va = *(const uint4*)&hin[(m0 + row)*64 + c8*8];
        *(uint4*)&sA[row*36 + c8*4] = va;
    }
    #pragma unroll
    for (int i = 0; i < 2; i++){
        int idx = tid + i*256;
        int row = idx >> 3;
        int c8  = idx & 7;
        uint4 vb = *(const uint4*)&W[row*64 + c8*8];
        *(uint4*)&sB[row*36 + c8*4] = vb;
    }
    __syncthreads();

    int wid = tid >> 5, lane = tid & 31;
    int g = lane >> 2, t4 = lane & 3;
    int wr = wid * 16;

    uint32_t aBase = smem_u32(sA) + (((wr + (lane & 15))*36 + ((lane & 16) ? 4 : 0)) << 2);
    uint32_t bBase = smem_u32(sB) + (((((lane >> 4) & 1)*8 + (lane & 7))*36 + ((lane >> 3) & 1)*4) << 2);

    float acc[8][4] = {};

    #pragma unroll
    for (int kc = 0; kc < 4; kc++){
        uint32_t a[4];
        ldsm_x4(a, aBase + kc*32);
        #pragma unroll
        for (int nt2 = 0; nt2 < 8; nt2 += 2){
            uint32_t b[4];
            ldsm_x4(b, bBase + nt2*1152 + kc*32);
            mma_f16(acc[nt2],   a, b[0], b[1]);
            mma_f16(acc[nt2+1], a, b[2], b[3]);
        }
    }

    // staged epilogue: regs -> smem (conflict-free) -> coalesced uint4 stores
    __syncthreads();
    __half* sOut = (__half*)sA;
    {
        int r0 = wr + g;
        #pragma unroll
        for (int nt = 0; nt < 8; nt++){
            int col = nt*8 + t4*2;
            float bz0 = bias[col], bz1 = bias[col+1];
            *(__half2*)&sOut[r0*72 + col]     = __floats2half2_rn(acc[nt][0] + bz0, acc[nt][1] + bz1);
            *(__half2*)&sOut[(r0+8)*72 + col] = __floats2half2_rn(acc[nt][2] + bz0, acc[nt][3] + bz1);
        }
    }
    __syncthreads();
    #pragma unroll
    for (int i = 0; i < 4; i++){
        int idx = tid + i*256;
        int row = idx >> 3;
        int c8  = idx & 7;
        if (m0 + row < NN)
            *(uint4*)&out[(m0 + row)*ldo + coff + c8*8] = *(uint4*)&sOut[row*72 + c8*8];
    }
}

// ---------------- edge kernel: per-dst warp, src-prefetch + shfl broadcast ----------------
// The CSR src list for a dst is contiguous: one coalesced 32-wide load per
// chunk fetches up to 32 indices; __shfl broadcasts them. kv gathers then
// have NO memory-dependent prologue -> full unroll-window of loads in flight.
__global__ void k_edge(int pp){
    int gw = (blockIdx.x*blockDim.x + threadIdx.x) >> 5;
    int lane = threadIdx.x & 31;
    if (gw >= NN) return;
    int dst = gw;
    __half* hout = pp ? g_h16 : g_hn16;

    uint4 qr = *(const uint4*)&g_q16[dst*256 + lane*8];
    __half2 sc = __float2half2_rn(0.125f);
    __half2 qh0 = __hmul2(*(__half2*)&qr.x, sc);
    __half2 qh1 = __hmul2(*(__half2*)&qr.y, sc);
    __half2 qh2 = __hmul2(*(__half2*)&qr.z, sc);
    __half2 qh3 = __hmul2(*(__half2*)&qr.w, sc);

    int beg = g_rowptr[dst], end = g_rowptr[dst+1];

    float ssum = 0.f;
    float acc[8] = {0,0,0,0,0,0,0,0};

    for (int p0 = beg; p0 < end; p0 += 32){
        int cnt = end - p0; if (cnt > 32) cnt = 32;
        int myS = (p0 + lane < end) ? g_srcs[p0 + lane] : 0;

        #pragma unroll 8
        for (int j = 0; j < cnt; j++){
            int s = __shfl_sync(0xffffffffu, myS, j);
            uint4 kr = *(const uint4*)&g_kv[s*512 + lane*8];
            uint4 vr = *(const uint4*)&g_kv[s*512 + 256 + lane*8];
            __half2 d2 = __hmul2(qh0, *(__half2*)&kr.x);
            d2 = __hfma2(qh1, *(__half2*)&kr.y, d2);
            d2 = __hfma2(qh2, *(__half2*)&kr.z, d2);
            d2 = __hfma2(qh3, *(__half2*)&kr.w, d2);
            float2 df = __half22float2(d2);
            float d = df.x + df.y;
            d += __shfl_xor_sync(0xffffffffu, d, 1);
            d += __shfl_xor_sync(0xffffffffu, d, 2);
            d += __shfl_xor_sync(0xffffffffu, d, 4);
            float e = __expf(d);
            ssum += e;
            float2 v0 = __half22float2(*(__half2*)&vr.x);
            float2 v1 = __half22float2(*(__half2*)&vr.y);
            float2 v2 = __half22float2(*(__half2*)&vr.z);
            float2 v3 = __half22float2(*(__half2*)&vr.w);
            acc[0] += e*v0.x; acc[1] += e*v0.y;
            acc[2] += e*v1.x; acc[3] += e*v1.y;
            acc[4] += e*v2.x; acc[5] += e*v2.y;
            acc[6] += e*v3.x; acc[7] += e*v3.y;
        }
    }

    float inv = (end > beg) ? 1.f / ssum : 0.f;
    #pragma unroll
    for (int j = 0; j < 8; j++){
        float aj = acc[j] * inv;
        aj += __shfl_xor_sync(0xffffffffu, aj, 8);
        aj += __shfl_xor_sync(0xffffffffu, aj, 16);
        acc[j] = aj;
    }
    if (lane < 8){
        uint4 sr = *(const uint4*)&g_s16[dst*64 + lane*8];
        float2 s0 = __half22float2(*(__half2*)&sr.x);
        float2 s1 = __half22float2(*(__half2*)&sr.y);
        float2 s2 = __half22float2(*(__half2*)&sr.z);
        float2 s3 = __half22float2(*(__half2*)&sr.w);
        float o0 = elu(acc[0]*0.25f + s0.x), o1 = elu(acc[1]*0.25f + s0.y);
        float o2 = elu(acc[2]*0.25f + s1.x), o3 = elu(acc[3]*0.25f + s1.y);
        float o4 = elu(acc[4]*0.25f + s2.x), o5 = elu(acc[5]*0.25f + s2.y);
        float o6 = elu(acc[6]*0.25f + s3.x), o7 = elu(acc[7]*0.25f + s3.y);
        uint4 hw;
        *(__half2*)&hw.x = __floats2half2_rn(o0, o1);
        *(__half2*)&hw.y = __floats2half2_rn(o2, o3);
        *(__half2*)&hw.z = __floats2half2_rn(o4, o5);
        *(__half2*)&hw.w = __floats2half2_rn(o6, o7);
        *(uint4*)&hout[dst*64 + lane*8] = hw;
    }
}

// ---------------- output MLP: 64 -> 64 -> 32 -> 8 ----------------
__global__ void k_out(const float* __restrict__ w1, const float* __restrict__ b1,
                      const float* __restrict__ w2, const float* __restrict__ b2,
                      const float* __restrict__ w3, const float* __restrict__ b3,
                      float* __restrict__ out){
    __shared__ float sw1[64*64];
    __shared__ float sw2[64*32];
    __shared__ float sw3[32*8];
    __shared__ float sb1[64], sb2[32], sb3[8];
    __shared__ float so1[4][64];
    __shared__ float so2[4][32];
    int tid = threadIdx.x;
    #pragma unroll
    for (int i = 0; i < 16; i++){
        int idx = tid + i*256;
        sw1[(idx & 63)*64 + (idx >> 6)] = w1[idx];
    }
    #pragma unroll
    for (int i = 0; i < 8; i++){
        int idx = tid + i*256;
        sw2[(idx & 63)*32 + (idx >> 6)] = w2[idx];
    }
    { int idx = tid;
      sw3[(idx & 31)*8 + (idx >> 5)] = w3[idx]; }
    if (tid < 64) sb1[tid] = b1[tid];
    if (tid < 32) sb2[tid] = b2[tid];
    if (tid < 8)  sb3[tid] = b3[tid];
    __syncthreads();

    int u = tid & 63, nl = tid >> 6;
    int n0 = blockIdx.x * 32;
    for (int it = 0; it < 8; ++it){
        int n = n0 + it*4 + nl;
        float o1v = 0.f;
        if (n < NN){
            float s = sb1[u];
            #pragma unroll
            for (int k = 0; k < 64; k++) s += __half2float(g_h16[n*64 + k]) * sw1[k*64 + u];
            o1v = elu(s);
        }
        so1[nl][u] = o1v;
        __syncthreads();
        if (u < 32 && n < NN){
            float s = sb2[u];
            #pragma unroll
            for (int k = 0; k < 64; k++) s += so1[nl][k] * sw2[k*32 + u];
            so2[nl][u] = elu(s);
        }
        __syncthreads();
        if (u < 8 && n < NN){
            float s = sb3[u];
            #pragma unroll
            for (int k = 0; k < 32; k++) s += so2[nl][k] * sw3[k*8 + u];
            out[n*8 + u] = s;
        }
        __syncthreads();
    }
}

// ---------------- launch ----------------
extern "C" void kernel_launch(void* const* d_in, const int* in_sizes, int n_in,
                              void* d_out, int out_size){
    const float* x   = (const float*)d_in[0];
    const int*   ei  = (const int*)d_in[1];
    const float* enc_w1 = (const float*)d_in[2];
    const float* enc_b1 = (const float*)d_in[3];
    const float* enc_w2 = (const float*)d_in[4];
    const float* enc_b2 = (const float*)d_in[5];
    const float* Wq = (const float*)d_in[6];
    const float* bq = (const float*)d_in[7];
    const float* Wk = (const float*)d_in[8];
    const float* bk = (const float*)d_in[9];
    const float* Wv = (const float*)d_in[10];
    const float* bv = (const float*)d_in[11];
    const float* Ws = (const float*)d_in[12];
    const float* bs = (const float*)d_in[13];
    const float* ow1 = (const float*)d_in[14];
    const float* ob1 = (const float*)d_in[15];
    const float* ow2 = (const float*)d_in[16];
    const float* ob2 = (const float*)d_in[17];
    const float* ow3 = (const float*)d_in[18];
    const float* ob3 = (const float*)d_in[19];
    float* out = (float*)d_out;

    dim3 ggrid((NN+127)/128, 13);

    // launch order matches the proven 581.7us configuration
    k_wconv<<<(4*13*4096+255)/256, 256>>>(Wq, Wk, Wv, Ws);          // 0
    k_encoder<<<(NN+63)/64, 256>>>(x, enc_w1, enc_b1, enc_w2, enc_b2); // 1
    k_zero_deg<<<(NN+255)/256, 256>>>();                            // 2
    k_gemm<<<ggrid, 256>>>(0, 0, bq, bk, bv, bs);                   // 3 <- ncu
    k_hist<<<(EE+255)/256, 256>>>(ei);                              // 4
    k_scan<<<1, 1024>>>();                                          // 5
    k_fill<<<(EE+255)/256, 256>>>(ei);                              // 6
    k_edge<<<(NN*32 + 255)/256, 256>>>(0);                          // 7

    for (int l = 1; l < 4; l++){
        int pp = l & 1;
        k_gemm<<<ggrid, 256>>>(l, pp, bq + l*256, bk + l*256, bv + l*256, bs + l*64);
        k_edge<<<(NN*32 + 255)/256, 256>>>(pp);
    }

    // output MLP (final h is in g_h16 after layer 3)
    k_out<<<(NN+31)/32, 256>>>(ow1, ob1, ow2, ob2, ow3, ob3, out);
}